// round 1
// baseline (speedup 1.0000x reference)
#include <cuda_runtime.h>
#include <cuda_fp16.h>
#include <cstdint>
#include <cstddef>

#define N_NODES 8192
#define IN_DIM  256
#define OUT_DIM 128
#define ALPHA   0.2f
#define MT      64      // rows per CTA
#define KT      128     // j per tile

#define WS_STRIDE (KT + 8)       // 136 halves -> 272B rows, odd 16B-unit stride (conflict-free ldmatrix)
#define BS_STRIDE (OUT_DIM + 8)  // 136 halves
#define SMEM_BYTES (MT * WS_STRIDE * 2 + KT * BS_STRIDE * 2)  // 17408 + 34816 = 52224

// Scratch (device globals: no allocation allowed)
__device__ float  g_Wh [N_NODES * OUT_DIM];
__device__ __half g_Whh[N_NODES * OUT_DIM];
__device__ float  g_f1 [N_NODES];
__device__ float  g_f2 [N_NODES];
__device__ float  g_M  [N_NODES];
__device__ float  g_c;

// ---------------------------------------------------------------------------
// Kernel 1: Wh = X @ W (fp32 + fp16 copy), f1 = Wh@a1, f2 = Wh@a2
// one block per row, 128 threads = one output column each
// ---------------------------------------------------------------------------
__global__ __launch_bounds__(128) void k_wh(const float* __restrict__ X,
                                            const float* __restrict__ W,
                                            const float* __restrict__ a) {
    int i = blockIdx.x, c = threadIdx.x;
    __shared__ float xs[IN_DIM];
    __shared__ float red[8];
    xs[c]       = X[(size_t)i * IN_DIM + c];
    xs[c + 128] = X[(size_t)i * IN_DIM + 128 + c];
    __syncthreads();
    float acc = 0.f;
#pragma unroll 16
    for (int k = 0; k < IN_DIM; k++)
        acc = fmaf(xs[k], W[k * OUT_DIM + c], acc);
    g_Wh [(size_t)i * OUT_DIM + c] = acc;
    g_Whh[(size_t)i * OUT_DIM + c] = __float2half_rn(acc);
    float v1 = acc * a[c];
    float v2 = acc * a[OUT_DIM + c];
#pragma unroll
    for (int off = 16; off; off >>= 1) {
        v1 += __shfl_xor_sync(0xffffffffu, v1, off);
        v2 += __shfl_xor_sync(0xffffffffu, v2, off);
    }
    if ((c & 31) == 0) { red[c >> 5] = v1; red[4 + (c >> 5)] = v2; }
    __syncthreads();
    if (c == 0) g_f1[i] = red[0] + red[1] + red[2] + red[3];
    if (c == 1) g_f2[i] = red[4] + red[5] + red[6] + red[7];
}

// ---------------------------------------------------------------------------
// Kernel 2: g_c = max_j f2[j]
// ---------------------------------------------------------------------------
__global__ __launch_bounds__(256) void k_max() {
    __shared__ float red[8];
    int t = threadIdx.x;
    float m = -1e30f;
    for (int i = t; i < N_NODES; i += 256) m = fmaxf(m, g_f2[i]);
#pragma unroll
    for (int off = 16; off; off >>= 1) m = fmaxf(m, __shfl_xor_sync(0xffffffffu, m, off));
    if ((t & 31) == 0) red[t >> 5] = m;
    __syncthreads();
    if (t == 0) {
        float mm = red[0];
#pragma unroll
        for (int i = 1; i < 8; i++) mm = fmaxf(mm, red[i]);
        g_c = mm;
    }
}

// ---------------------------------------------------------------------------
// Kernel 3: per-row stable offset M_i = lrelu(f1_i + max f2). Monotone lrelu
// guarantees M_i >= every admissible score of row i -> exp(e - M_i) <= 1.
// ---------------------------------------------------------------------------
__global__ __launch_bounds__(256) void k_prep() {
    int i = blockIdx.x * 256 + threadIdx.x;
    float s = g_f1[i] + g_c;
    g_M[i] = fmaxf(s, ALPHA * s);
}

__device__ __forceinline__ uint32_t s2u(const void* p) {
    return (uint32_t)__cvta_generic_to_shared(p);
}

__device__ __forceinline__ void mma16816(float* d, uint32_t a0, uint32_t a1, uint32_t a2,
                                         uint32_t a3, uint32_t b0, uint32_t b1) {
    asm volatile(
        "mma.sync.aligned.m16n8k16.row.col.f32.f16.f16.f32 "
        "{%0,%1,%2,%3},{%4,%5,%6,%7},{%8,%9},{%0,%1,%2,%3};\n"
        : "+f"(d[0]), "+f"(d[1]), "+f"(d[2]), "+f"(d[3])
        : "r"(a0), "r"(a1), "r"(a2), "r"(a3), "r"(b0), "r"(b1));
}

// ---------------------------------------------------------------------------
// Kernel 4: main fused kernel. CTA = 64 output rows x 128 cols.
// Per j-tile (128): build W tile (fp16) on the fly from adjacency + f1/f2,
// stage Wh tile, then 64x128x128 fp16 MMA. No online softmax needed.
// ---------------------------------------------------------------------------
__global__ __launch_bounds__(256, 1) void k_main(const int* __restrict__ adj,
                                                 float* __restrict__ out) {
    extern __shared__ __align__(16) char smem[];
    __half(*Ws)[WS_STRIDE] = reinterpret_cast<__half(*)[WS_STRIDE]>(smem);
    __half(*Bs)[BS_STRIDE] = reinterpret_cast<__half(*)[BS_STRIDE]>(smem + MT * WS_STRIDE * 2);

    const int tid  = threadIdx.x;
    const int lane = tid & 31, wid = tid >> 5;
    const int wm = wid & 3;   // 4 row-slices of 16
    const int wn = wid >> 2;  // 2 col-slices of 64
    const int i0 = blockIdx.x * MT;

    // w-generation mapping: 4 threads per row, each covers 32 contiguous j
    const int r  = tid >> 2;
    const int jq = tid & 3;
    // B-load mapping: 2 threads per j-row, each 64 halves
    const int jb   = tid >> 1;
    const int boff = (tid & 1) * 64;

    const float f1r = g_f1[i0 + r];
    const float Mr  = g_M[i0 + r];

    const int* arow = adj + (size_t)(i0 + r) * N_NODES + jq * 32;

    int4 AV[8];
#pragma unroll
    for (int q = 0; q < 8; q++)
        AV[q] = *reinterpret_cast<const int4*>(arow + q * 4);

    float acc[8][4];
#pragma unroll
    for (int n = 0; n < 8; n++)
#pragma unroll
        for (int e = 0; e < 4; e++) acc[n][e] = 0.f;
    float Spart = 0.f;

    for (int jt = 0; jt < N_NODES; jt += KT) {
        // stage Wh tile (fp16, from L2-resident g_Whh) into registers first
        uint4 BV[8];
        const uint4* bsrc =
            reinterpret_cast<const uint4*>(g_Whh + (size_t)(jt + jb) * OUT_DIM + boff);
#pragma unroll
        for (int q = 0; q < 8; q++) BV[q] = bsrc[q];

        // generate attention-weight tile from prefetched adjacency
#pragma unroll
        for (int q = 0; q < 8; q++) {
            float4 f2v = *reinterpret_cast<const float4*>(g_f2 + jt + jq * 32 + q * 4);
            int4 av = AV[q];
            float s0 = f1r + f2v.x, s1 = f1r + f2v.y;
            float s2 = f1r + f2v.z, s3 = f1r + f2v.w;
            float w0 = (av.x > 0) ? __expf(fmaxf(s0, ALPHA * s0) - Mr) : 0.f;
            float w1 = (av.y > 0) ? __expf(fmaxf(s1, ALPHA * s1) - Mr) : 0.f;
            float w2 = (av.z > 0) ? __expf(fmaxf(s2, ALPHA * s2) - Mr) : 0.f;
            float w3 = (av.w > 0) ? __expf(fmaxf(s3, ALPHA * s3) - Mr) : 0.f;
            __half2 h01 = __floats2half2_rn(w0, w1);
            __half2 h23 = __floats2half2_rn(w2, w3);
            *reinterpret_cast<__half2*>(&Ws[r][jq * 32 + q * 4])     = h01;
            *reinterpret_cast<__half2*>(&Ws[r][jq * 32 + q * 4 + 2]) = h23;
            // sum the fp16-ROUNDED values so numerator/denominator errors cancel
            float2 c01 = __half22float2(h01), c23 = __half22float2(h23);
            Spart += (c01.x + c01.y) + (c23.x + c23.y);
        }

#pragma unroll
        for (int q = 0; q < 8; q++)
            *reinterpret_cast<uint4*>(&Bs[jb][boff + q * 8]) = BV[q];

        // prefetch next adjacency tile: HBM latency hides under the MMA phase
        if (jt + KT < N_NODES) {
#pragma unroll
            for (int q = 0; q < 8; q++)
                AV[q] = *reinterpret_cast<const int4*>(arow + (jt + KT) + q * 4);
        }
        __syncthreads();

        // MMA phase: 8 k-steps of m16n8k16 over the 64x128 @ 128x128 tile
#pragma unroll
        for (int ks = 0; ks < KT / 16; ks++) {
            uint32_t a0, a1, a2, a3;
            uint32_t aaddr = s2u(&Ws[wm * 16 + (lane & 15)][ks * 16 + (lane >> 4) * 8]);
            asm volatile("ldmatrix.sync.aligned.m8n8.x4.shared.b16 {%0,%1,%2,%3}, [%4];"
                         : "=r"(a0), "=r"(a1), "=r"(a2), "=r"(a3)
                         : "r"(aaddr));
#pragma unroll
            for (int bn = 0; bn < 4; bn++) {
                uint32_t b0, b1, b2, b3;
                uint32_t baddr =
                    s2u(&Bs[ks * 16 + (lane & 15)][wn * 64 + bn * 16 + (lane >> 4) * 8]);
                asm volatile("ldmatrix.sync.aligned.m8n8.x4.trans.shared.b16 {%0,%1,%2,%3}, [%4];"
                             : "=r"(b0), "=r"(b1), "=r"(b2), "=r"(b3)
                             : "r"(baddr));
                mma16816(acc[2 * bn],     a0, a1, a2, a3, b0, b1);
                mma16816(acc[2 * bn + 1], a0, a1, a2, a3, b2, b3);
            }
        }
        __syncthreads();
    }

    // row-sum reduction (4 partials per row), reusing Ws smem
    float* Ssum = reinterpret_cast<float*>(smem);
    Ssum[r * 4 + jq] = Spart;
    __syncthreads();

    const int g    = lane >> 2;
    const int row0 = wm * 16 + g;
    const int row1 = row0 + 8;
    float S0 = Ssum[row0 * 4] + Ssum[row0 * 4 + 1] + Ssum[row0 * 4 + 2] + Ssum[row0 * 4 + 3];
    float S1 = Ssum[row1 * 4] + Ssum[row1 * 4 + 1] + Ssum[row1 * 4 + 2] + Ssum[row1 * 4 + 3];
    float inv0 = 1.f / S0, inv1 = 1.f / S1;

#pragma unroll
    for (int nt = 0; nt < 8; nt++) {
        int cn = wn * 64 + nt * 8 + 2 * (lane & 3);
        size_t o0 = (size_t)(i0 + row0) * OUT_DIM + cn;
        size_t o1 = (size_t)(i0 + row1) * OUT_DIM + cn;
        float v;
        v = acc[nt][0] * inv0; out[o0]     = v > 0.f ? v : __expf(v) - 1.f;
        v = acc[nt][1] * inv0; out[o0 + 1] = v > 0.f ? v : __expf(v) - 1.f;
        v = acc[nt][2] * inv1; out[o1]     = v > 0.f ? v : __expf(v) - 1.f;
        v = acc[nt][3] * inv1; out[o1 + 1] = v > 0.f ? v : __expf(v) - 1.f;
    }
}

// ---------------------------------------------------------------------------
extern "C" void kernel_launch(void* const* d_in, const int* in_sizes, int n_in,
                              void* d_out, int out_size) {
    const int*   adj = (const int*)d_in[0];
    const float* X   = (const float*)d_in[1];
    const float* W   = (const float*)d_in[2];
    const float* a   = (const float*)d_in[3];
    float* out = (float*)d_out;

    cudaFuncSetAttribute(k_main, cudaFuncAttributeMaxDynamicSharedMemorySize, SMEM_BYTES);

    k_wh<<<N_NODES, 128>>>(X, W, a);
    k_max<<<1, 256>>>();
    k_prep<<<N_NODES / 256, 256>>>();
    k_main<<<N_NODES / MT, 256, SMEM_BYTES>>>(adj, out);
}

// round 2
// speedup vs baseline: 1.0615x; 1.0615x over previous
#include <cuda_runtime.h>
#include <cuda_fp16.h>
#include <cstdint>
#include <cstddef>

#define N_NODES 8192
#define IN_DIM  256
#define OUT_DIM 128
#define ALPHA   0.2f
#define MT      64      // rows per CTA
#define KT      128     // j per tile
#define NTILES  (N_NODES / KT)   // 64

#define WS_STRIDE (KT + 8)       // 136 halves (odd 16B-unit stride, conflict-free ldmatrix)
#define BS_STRIDE (OUT_DIM + 8)  // 136 halves
#define WS_BYTES  (MT * WS_STRIDE * 2)   // 17408
#define BS_BYTES  (KT * BS_STRIDE * 2)   // 34816
#define SMEM_BYTES (2 * WS_BYTES + 2 * BS_BYTES)  // 104448

// Scratch (device globals: no allocation allowed)
__device__ __half g_Whh[N_NODES * OUT_DIM];
__device__ float  g_f1 [N_NODES];
__device__ float  g_f2 [N_NODES];
__device__ float  g_M  [N_NODES];
__device__ float  g_c;

// ---------------------------------------------------------------------------
// Kernel 1: Wh = X @ W (fp16 copy), f1 = Wh@a1, f2 = Wh@a2
// 16 rows per block, 256 threads: thread = (32 col-groups of 4) x (8 row-pairs)
// Each W LDG.128 is reused for 8 FMAs (2 rows x 4 cols) -> LSU pressure /8.
// ---------------------------------------------------------------------------
__global__ __launch_bounds__(256) void k_wh(const float* __restrict__ X,
                                            const float* __restrict__ W,
                                            const float* __restrict__ a) {
    __shared__ float xs[16][IN_DIM];
    const int tid = threadIdx.x;
    const int i0  = blockIdx.x * 16;

    // cooperative load of 16 rows of X (16*256 floats = 1024 float4)
    const float4* Xv  = reinterpret_cast<const float4*>(X + (size_t)i0 * IN_DIM);
    float4*       xsv = reinterpret_cast<float4*>(&xs[0][0]);
#pragma unroll
    for (int q = 0; q < 4; q++) xsv[tid + q * 256] = Xv[tid + q * 256];
    __syncthreads();

    const int cg = tid & 31;        // column group (4 cols)
    const int rp = tid >> 5;        // row pair 0..7  (one warp per row pair)
    const int r0 = rp * 2, r1 = r0 + 1;
    const int c4 = cg * 4;

    const float4* Wv = reinterpret_cast<const float4*>(W);  // row k: 32 float4
    float4 acc0 = {0.f, 0.f, 0.f, 0.f};
    float4 acc1 = {0.f, 0.f, 0.f, 0.f};
#pragma unroll 8
    for (int k = 0; k < IN_DIM; k++) {
        float4 w  = Wv[k * 32 + cg];
        float  x0 = xs[r0][k];     // broadcast within warp
        float  x1 = xs[r1][k];
        acc0.x = fmaf(x0, w.x, acc0.x); acc0.y = fmaf(x0, w.y, acc0.y);
        acc0.z = fmaf(x0, w.z, acc0.z); acc0.w = fmaf(x0, w.w, acc0.w);
        acc1.x = fmaf(x1, w.x, acc1.x); acc1.y = fmaf(x1, w.y, acc1.y);
        acc1.z = fmaf(x1, w.z, acc1.z); acc1.w = fmaf(x1, w.w, acc1.w);
    }

    // store fp16 Wh (8B per row-slot)
    {
        __half2 h00 = __floats2half2_rn(acc0.x, acc0.y);
        __half2 h01 = __floats2half2_rn(acc0.z, acc0.w);
        __half2 h10 = __floats2half2_rn(acc1.x, acc1.y);
        __half2 h11 = __floats2half2_rn(acc1.z, acc1.w);
        __half2* p0 = reinterpret_cast<__half2*>(g_Whh + (size_t)(i0 + r0) * OUT_DIM + c4);
        __half2* p1 = reinterpret_cast<__half2*>(g_Whh + (size_t)(i0 + r1) * OUT_DIM + c4);
        p0[0] = h00; p0[1] = h01;
        p1[0] = h10; p1[1] = h11;
    }

    // f1/f2 partials: dot with a1 (a[0:128]) and a2 (a[128:256])
    float p1 = acc0.x * a[c4] + acc0.y * a[c4 + 1] + acc0.z * a[c4 + 2] + acc0.w * a[c4 + 3];
    float q1 = acc0.x * a[128 + c4] + acc0.y * a[128 + c4 + 1] +
               acc0.z * a[128 + c4 + 2] + acc0.w * a[128 + c4 + 3];
    float p2 = acc1.x * a[c4] + acc1.y * a[c4 + 1] + acc1.z * a[c4 + 2] + acc1.w * a[c4 + 3];
    float q2 = acc1.x * a[128 + c4] + acc1.y * a[128 + c4 + 1] +
               acc1.z * a[128 + c4 + 2] + acc1.w * a[128 + c4 + 3];
#pragma unroll
    for (int off = 16; off; off >>= 1) {
        p1 += __shfl_xor_sync(0xffffffffu, p1, off);
        q1 += __shfl_xor_sync(0xffffffffu, q1, off);
        p2 += __shfl_xor_sync(0xffffffffu, p2, off);
        q2 += __shfl_xor_sync(0xffffffffu, q2, off);
    }
    if (cg == 0) {
        g_f1[i0 + r0] = p1; g_f2[i0 + r0] = q1;
        g_f1[i0 + r1] = p2; g_f2[i0 + r1] = q2;
    }
}

// ---------------------------------------------------------------------------
// Kernel 2: g_c = max_j f2[j]
// ---------------------------------------------------------------------------
__global__ __launch_bounds__(256) void k_max() {
    __shared__ float red[8];
    int t = threadIdx.x;
    float m = -1e30f;
    for (int i = t; i < N_NODES; i += 256) m = fmaxf(m, g_f2[i]);
#pragma unroll
    for (int off = 16; off; off >>= 1) m = fmaxf(m, __shfl_xor_sync(0xffffffffu, m, off));
    if ((t & 31) == 0) red[t >> 5] = m;
    __syncthreads();
    if (t == 0) {
        float mm = red[0];
#pragma unroll
        for (int i = 1; i < 8; i++) mm = fmaxf(mm, red[i]);
        g_c = mm;
    }
}

// ---------------------------------------------------------------------------
// Kernel 3: per-row stable offset M_i = lrelu(f1_i + max f2) >= all scores of row i
// ---------------------------------------------------------------------------
__global__ __launch_bounds__(256) void k_prep() {
    int i = blockIdx.x * 256 + threadIdx.x;
    float s = g_f1[i] + g_c;
    g_M[i] = fmaxf(s, ALPHA * s);
}

__device__ __forceinline__ uint32_t s2u(const void* p) {
    return (uint32_t)__cvta_generic_to_shared(p);
}

__device__ __forceinline__ void cpasync16(uint32_t dst, const void* src) {
    asm volatile("cp.async.cg.shared.global [%0], [%1], 16;\n" :: "r"(dst), "l"(src));
}
#define CP_COMMIT() asm volatile("cp.async.commit_group;\n" ::: "memory")
#define CP_WAIT0()  asm volatile("cp.async.wait_group 0;\n" ::: "memory")

__device__ __forceinline__ void mma16816(float* d, uint32_t a0, uint32_t a1, uint32_t a2,
                                         uint32_t a3, uint32_t b0, uint32_t b1) {
    asm volatile(
        "mma.sync.aligned.m16n8k16.row.col.f32.f16.f16.f32 "
        "{%0,%1,%2,%3},{%4,%5,%6,%7},{%8,%9},{%0,%1,%2,%3};\n"
        : "+f"(d[0]), "+f"(d[1]), "+f"(d[2]), "+f"(d[3])
        : "r"(a0), "r"(a1), "r"(a2), "r"(a3), "r"(b0), "r"(b1));
}

// generate one 64x128 attention-weight tile (fp16) from adjacency + f1/f2
__device__ __forceinline__ void gen_tile(const int4* AV, int jt,
                                         __half (*WsB)[WS_STRIDE],
                                         int r, int jq, float f1r, float Mr,
                                         float& Spart) {
#pragma unroll
    for (int q = 0; q < 8; q++) {
        float4 f2v = *reinterpret_cast<const float4*>(g_f2 + jt + jq * 32 + q * 4);
        int4 av = AV[q];
        float s0 = f1r + f2v.x, s1 = f1r + f2v.y;
        float s2 = f1r + f2v.z, s3 = f1r + f2v.w;
        float w0 = (av.x > 0) ? __expf(fmaxf(s0, ALPHA * s0) - Mr) : 0.f;
        float w1 = (av.y > 0) ? __expf(fmaxf(s1, ALPHA * s1) - Mr) : 0.f;
        float w2 = (av.z > 0) ? __expf(fmaxf(s2, ALPHA * s2) - Mr) : 0.f;
        float w3 = (av.w > 0) ? __expf(fmaxf(s3, ALPHA * s3) - Mr) : 0.f;
        __half2 h01 = __floats2half2_rn(w0, w1);
        __half2 h23 = __floats2half2_rn(w2, w3);
        *reinterpret_cast<__half2*>(&WsB[r][jq * 32 + q * 4])     = h01;
        *reinterpret_cast<__half2*>(&WsB[r][jq * 32 + q * 4 + 2]) = h23;
        // sum the fp16-ROUNDED values so numerator/denominator errors cancel
        float2 c01 = __half22float2(h01), c23 = __half22float2(h23);
        Spart += (c01.x + c01.y) + (c23.x + c23.y);
    }
}

// ---------------------------------------------------------------------------
// Kernel 4: fused masked-softmax @ Wh, software-pipelined.
// Per phase: issue cp.async for next Wh tile, issue adjacency LDG two tiles
// ahead, run MMA on current buffers, generate next W tile, one barrier.
// ---------------------------------------------------------------------------
__global__ __launch_bounds__(256, 1) void k_main(const int* __restrict__ adj,
                                                 float* __restrict__ out) {
    extern __shared__ __align__(16) char smem[];
    __half(*Ws0)[WS_STRIDE] = reinterpret_cast<__half(*)[WS_STRIDE]>(smem);
    __half(*Ws1)[WS_STRIDE] = reinterpret_cast<__half(*)[WS_STRIDE]>(smem + WS_BYTES);
    __half(*Bs0)[BS_STRIDE] = reinterpret_cast<__half(*)[BS_STRIDE]>(smem + 2 * WS_BYTES);
    __half(*Bs1)[BS_STRIDE] = reinterpret_cast<__half(*)[BS_STRIDE]>(smem + 2 * WS_BYTES + BS_BYTES);
    __half(*WsA[2])[WS_STRIDE] = {Ws0, Ws1};
    __half(*BsA[2])[BS_STRIDE] = {Bs0, Bs1};

    const int tid  = threadIdx.x;
    const int lane = tid & 31, wid = tid >> 5;
    const int wm = wid & 3;   // 4 row-slices of 16
    const int wn = wid >> 2;  // 2 col-slices of 64
    const int i0 = blockIdx.x * MT;

    // gen mapping: 4 threads per row, 32 contiguous j each
    const int r  = tid >> 2;
    const int jq = tid & 3;
    // Bs cp.async mapping: 2 threads per j-row, 64 halves each
    const int jb   = tid >> 1;
    const int boff = (tid & 1) * 64;

    const float f1r = g_f1[i0 + r];
    const float Mr  = g_M[i0 + r];
    const int* arow = adj + (size_t)(i0 + r) * N_NODES + jq * 32;

    const uint32_t bdst[2] = {s2u(&Bs0[jb][boff]), s2u(&Bs1[jb][boff])};
    const __half* bsrc_base = g_Whh + (size_t)jb * OUT_DIM + boff;

    float acc[8][4];
#pragma unroll
    for (int n = 0; n < 8; n++)
#pragma unroll
        for (int e = 0; e < 4; e++) acc[n][e] = 0.f;
    float Spart = 0.f;

    int4 AV[2][8];

    // ---- prologue: tile0 -> Ws0/Bs0, AV[1] holds adjacency tile1 ----
#pragma unroll
    for (int q = 0; q < 8; q++) AV[0][q] = *reinterpret_cast<const int4*>(arow + q * 4);
#pragma unroll
    for (int q = 0; q < 8; q++) cpasync16(bdst[0] + q * 16, bsrc_base + q * 8);
    CP_COMMIT();
#pragma unroll
    for (int q = 0; q < 8; q++) AV[1][q] = *reinterpret_cast<const int4*>(arow + KT + q * 4);
    gen_tile(AV[0], 0, Ws0, r, jq, f1r, Mr, Spart);
    CP_WAIT0();
    __syncthreads();

#pragma unroll 1
    for (int t = 0; t < NTILES; t += 2) {
#pragma unroll
        for (int ph = 0; ph < 2; ph++) {
            const int cur = t + ph;
            __half(*WsC)[WS_STRIDE] = WsA[ph];
            __half(*BsC)[BS_STRIDE] = BsA[ph];

            // 1. async-load next Wh tile into the other Bs buffer
            if (cur + 1 < NTILES) {
                const __half* bsrc = bsrc_base + (size_t)(cur + 1) * KT * OUT_DIM;
#pragma unroll
                for (int q = 0; q < 8; q++) cpasync16(bdst[ph ^ 1] + q * 16, bsrc + q * 8);
                CP_COMMIT();
            }
            // 2. adjacency LDG two tiles ahead (consumed next phase's gen)
            if (cur + 2 < NTILES) {
#pragma unroll
                for (int q = 0; q < 8; q++)
                    AV[ph][q] = *reinterpret_cast<const int4*>(arow + (cur + 2) * KT + q * 4);
            }
            // 3. MMA on current buffers
#pragma unroll
            for (int ks = 0; ks < KT / 16; ks++) {
                uint32_t a0, a1, a2, a3;
                uint32_t aaddr = s2u(&WsC[wm * 16 + (lane & 15)][ks * 16 + (lane >> 4) * 8]);
                asm volatile("ldmatrix.sync.aligned.m8n8.x4.shared.b16 {%0,%1,%2,%3}, [%4];"
                             : "=r"(a0), "=r"(a1), "=r"(a2), "=r"(a3)
                             : "r"(aaddr));
#pragma unroll
                for (int bn = 0; bn < 4; bn++) {
                    uint32_t b0, b1, b2, b3;
                    uint32_t baddr =
                        s2u(&BsC[ks * 16 + (lane & 15)][wn * 64 + bn * 16 + (lane >> 4) * 8]);
                    asm volatile("ldmatrix.sync.aligned.m8n8.x4.trans.shared.b16 {%0,%1,%2,%3}, [%4];"
                                 : "=r"(b0), "=r"(b1), "=r"(b2), "=r"(b3)
                                 : "r"(baddr));
                    mma16816(acc[2 * bn],     a0, a1, a2, a3, b0, b1);
                    mma16816(acc[2 * bn + 1], a0, a1, a2, a3, b2, b3);
                }
            }
            // 4. generate next W tile into the other Ws buffer
            if (cur + 1 < NTILES)
                gen_tile(AV[ph ^ 1], (cur + 1) * KT, WsA[ph ^ 1], r, jq, f1r, Mr, Spart);
            // 5. drain cp.async, fence the tile swap
            CP_WAIT0();
            __syncthreads();
        }
    }

    // ---- epilogue: row-sum reduction (4 partials/row), softmax scale, ELU ----
    float* Ssum = reinterpret_cast<float*>(smem);
    Ssum[r * 4 + jq] = Spart;
    __syncthreads();

    const int g    = lane >> 2;
    const int row0 = wm * 16 + g;
    const int row1 = row0 + 8;
    float S0 = Ssum[row0 * 4] + Ssum[row0 * 4 + 1] + Ssum[row0 * 4 + 2] + Ssum[row0 * 4 + 3];
    float S1 = Ssum[row1 * 4] + Ssum[row1 * 4 + 1] + Ssum[row1 * 4 + 2] + Ssum[row1 * 4 + 3];
    float inv0 = 1.f / S0, inv1 = 1.f / S1;

#pragma unroll
    for (int nt = 0; nt < 8; nt++) {
        int cn = wn * 64 + nt * 8 + 2 * (lane & 3);
        size_t o0 = (size_t)(i0 + row0) * OUT_DIM + cn;
        size_t o1 = (size_t)(i0 + row1) * OUT_DIM + cn;
        float v0 = acc[nt][0] * inv0, v1 = acc[nt][1] * inv0;
        float v2 = acc[nt][2] * inv1, v3 = acc[nt][3] * inv1;
        float2 r01 = make_float2(v0 > 0.f ? v0 : __expf(v0) - 1.f,
                                 v1 > 0.f ? v1 : __expf(v1) - 1.f);
        float2 r23 = make_float2(v2 > 0.f ? v2 : __expf(v2) - 1.f,
                                 v3 > 0.f ? v3 : __expf(v3) - 1.f);
        *reinterpret_cast<float2*>(out + o0) = r01;
        *reinterpret_cast<float2*>(out + o1) = r23;
    }
}

// ---------------------------------------------------------------------------
extern "C" void kernel_launch(void* const* d_in, const int* in_sizes, int n_in,
                              void* d_out, int out_size) {
    const int*   adj = (const int*)d_in[0];
    const float* X   = (const float*)d_in[1];
    const float* W   = (const float*)d_in[2];
    const float* a   = (const float*)d_in[3];
    float* out = (float*)d_out;

    cudaFuncSetAttribute(k_main, cudaFuncAttributeMaxDynamicSharedMemorySize, SMEM_BYTES);

    k_wh<<<N_NODES / 16, 256>>>(X, W, a);
    k_max<<<1, 256>>>();
    k_prep<<<N_NODES / 256, 256>>>();
    k_main<<<N_NODES / MT, 256, SMEM_BYTES>>>(adj, out);
}

// round 4
// speedup vs baseline: 1.0648x; 1.0031x over previous
#include <cuda_runtime.h>
#include <cuda_fp16.h>
#include <cstdint>
#include <cstddef>

#define N_NODES 8192
#define IN_DIM  256
#define OUT_DIM 128
#define ALPHA   0.2f
#define MT      64      // rows per CTA
#define KT      128     // j per tile
#define NTILES  (N_NODES / KT)   // 64

#define WS_STRIDE (KT + 8)       // 136 halves (272B rows, odd 16B multiple -> conflict-free ldmatrix)
#define BS_STRIDE (OUT_DIM + 8)  // 136 halves
#define AS_STRIDE 132            // ints; 528B = 16 mod 128 -> 8 consecutive rows hit 8 distinct 16B banks
#define WS_BYTES  (MT * WS_STRIDE * 2)    // 17408
#define BS_BYTES  (KT * BS_STRIDE * 2)    // 34816
#define AS_BYTES  (MT * AS_STRIDE * 4)    // 33792
#define SMEM_BYTES (2 * WS_BYTES + 2 * BS_BYTES + 3 * AS_BYTES)  // 205824

// Scratch (device globals: no allocation allowed)
__device__ __half g_Whh[N_NODES * OUT_DIM];
__device__ float  g_f1 [N_NODES];
__device__ float  g_f2 [N_NODES];
__device__ float  g_M  [N_NODES];
__device__ float  g_c;

// ---------------------------------------------------------------------------
// Kernel 1: Wh = X @ W (fp16), f1 = Wh@a1, f2 = Wh@a2
// ---------------------------------------------------------------------------
__global__ __launch_bounds__(256) void k_wh(const float* __restrict__ X,
                                            const float* __restrict__ W,
                                            const float* __restrict__ a) {
    __shared__ float xs[16][IN_DIM];
    const int tid = threadIdx.x;
    const int i0  = blockIdx.x * 16;

    const float4* Xv  = reinterpret_cast<const float4*>(X + (size_t)i0 * IN_DIM);
    float4*       xsv = reinterpret_cast<float4*>(&xs[0][0]);
#pragma unroll
    for (int q = 0; q < 4; q++) xsv[tid + q * 256] = Xv[tid + q * 256];
    __syncthreads();

    const int cg = tid & 31;
    const int rp = tid >> 5;
    const int r0 = rp * 2, r1 = r0 + 1;
    const int c4 = cg * 4;

    const float4* Wv = reinterpret_cast<const float4*>(W);
    float4 acc0 = {0.f, 0.f, 0.f, 0.f};
    float4 acc1 = {0.f, 0.f, 0.f, 0.f};
#pragma unroll 8
    for (int k = 0; k < IN_DIM; k++) {
        float4 w  = Wv[k * 32 + cg];
        float  x0 = xs[r0][k];
        float  x1 = xs[r1][k];
        acc0.x = fmaf(x0, w.x, acc0.x); acc0.y = fmaf(x0, w.y, acc0.y);
        acc0.z = fmaf(x0, w.z, acc0.z); acc0.w = fmaf(x0, w.w, acc0.w);
        acc1.x = fmaf(x1, w.x, acc1.x); acc1.y = fmaf(x1, w.y, acc1.y);
        acc1.z = fmaf(x1, w.z, acc1.z); acc1.w = fmaf(x1, w.w, acc1.w);
    }

    {
        __half2 h00 = __floats2half2_rn(acc0.x, acc0.y);
        __half2 h01 = __floats2half2_rn(acc0.z, acc0.w);
        __half2 h10 = __floats2half2_rn(acc1.x, acc1.y);
        __half2 h11 = __floats2half2_rn(acc1.z, acc1.w);
        __half2* p0 = reinterpret_cast<__half2*>(g_Whh + (size_t)(i0 + r0) * OUT_DIM + c4);
        __half2* p1 = reinterpret_cast<__half2*>(g_Whh + (size_t)(i0 + r1) * OUT_DIM + c4);
        p0[0] = h00; p0[1] = h01;
        p1[0] = h10; p1[1] = h11;
    }

    float p1 = acc0.x * a[c4] + acc0.y * a[c4 + 1] + acc0.z * a[c4 + 2] + acc0.w * a[c4 + 3];
    float q1 = acc0.x * a[128 + c4] + acc0.y * a[128 + c4 + 1] +
               acc0.z * a[128 + c4 + 2] + acc0.w * a[128 + c4 + 3];
    float p2 = acc1.x * a[c4] + acc1.y * a[c4 + 1] + acc1.z * a[c4 + 2] + acc1.w * a[c4 + 3];
    float q2 = acc1.x * a[128 + c4] + acc1.y * a[128 + c4 + 1] +
               acc1.z * a[128 + c4 + 2] + acc1.w * a[128 + c4 + 3];
#pragma unroll
    for (int off = 16; off; off >>= 1) {
        p1 += __shfl_xor_sync(0xffffffffu, p1, off);
        q1 += __shfl_xor_sync(0xffffffffu, q1, off);
        p2 += __shfl_xor_sync(0xffffffffu, p2, off);
        q2 += __shfl_xor_sync(0xffffffffu, q2, off);
    }
    if (cg == 0) {
        g_f1[i0 + r0] = p1; g_f2[i0 + r0] = q1;
        g_f1[i0 + r1] = p2; g_f2[i0 + r1] = q2;
    }
}

__global__ __launch_bounds__(256) void k_max() {
    __shared__ float red[8];
    int t = threadIdx.x;
    float m = -1e30f;
    for (int i = t; i < N_NODES; i += 256) m = fmaxf(m, g_f2[i]);
#pragma unroll
    for (int off = 16; off; off >>= 1) m = fmaxf(m, __shfl_xor_sync(0xffffffffu, m, off));
    if ((t & 31) == 0) red[t >> 5] = m;
    __syncthreads();
    if (t == 0) {
        float mm = red[0];
#pragma unroll
        for (int i = 1; i < 8; i++) mm = fmaxf(mm, red[i]);
        g_c = mm;
    }
}

__global__ __launch_bounds__(256) void k_prep() {
    int i = blockIdx.x * 256 + threadIdx.x;
    float s = g_f1[i] + g_c;
    g_M[i] = fmaxf(s, ALPHA * s);
}

__device__ __forceinline__ uint32_t s2u(const void* p) {
    return (uint32_t)__cvta_generic_to_shared(p);
}
__device__ __forceinline__ void cpasync16(uint32_t dst, const void* src) {
    asm volatile("cp.async.cg.shared.global [%0], [%1], 16;\n" :: "r"(dst), "l"(src));
}
#define CP_COMMIT() asm volatile("cp.async.commit_group;\n" ::: "memory")
#define CP_WAIT0()  asm volatile("cp.async.wait_group 0;\n" ::: "memory")
#define CP_WAIT1()  asm volatile("cp.async.wait_group 1;\n" ::: "memory")

__device__ __forceinline__ void mma16816(float* d, uint32_t a0, uint32_t a1, uint32_t a2,
                                         uint32_t a3, uint32_t b0, uint32_t b1) {
    asm volatile(
        "mma.sync.aligned.m16n8k16.row.col.f32.f16.f16.f32 "
        "{%0,%1,%2,%3},{%4,%5,%6,%7},{%8,%9},{%0,%1,%2,%3};\n"
        : "+f"(d[0]), "+f"(d[1]), "+f"(d[2]), "+f"(d[3])
        : "r"(a0), "r"(a1), "r"(a2), "r"(a3), "r"(b0), "r"(b1));
}

// generate one 64x128 fp16 attention-weight tile from SMEM adjacency + f1/f2
// thread map: r = tid&63 (row), jq = tid>>6 (32-j chunk) -> conflict-free LDS/STS
__device__ __forceinline__ void gen_tile(const int* __restrict__ As, int jt,
                                         __half (*WsB)[WS_STRIDE],
                                         int r, int jq, float f1r, float Mr,
                                         float& Spart) {
    const int* arow = As + r * AS_STRIDE + jq * 32;
#pragma unroll
    for (int q = 0; q < 8; q += 2) {
        uint32_t hh[4];
#pragma unroll
        for (int s = 0; s < 2; s++) {
            int4   av  = *reinterpret_cast<const int4*>(arow + (q + s) * 4);
            float4 f2v = *reinterpret_cast<const float4*>(g_f2 + jt + jq * 32 + (q + s) * 4);
            float s0 = f1r + f2v.x, s1 = f1r + f2v.y;
            float s2 = f1r + f2v.z, s3 = f1r + f2v.w;
            float w0 = (av.x > 0) ? __expf(fmaxf(s0, ALPHA * s0) - Mr) : 0.f;
            float w1 = (av.y > 0) ? __expf(fmaxf(s1, ALPHA * s1) - Mr) : 0.f;
            float w2 = (av.z > 0) ? __expf(fmaxf(s2, ALPHA * s2) - Mr) : 0.f;
            float w3 = (av.w > 0) ? __expf(fmaxf(s3, ALPHA * s3) - Mr) : 0.f;
            __half2 h01 = __floats2half2_rn(w0, w1);
            __half2 h23 = __floats2half2_rn(w2, w3);
            hh[s * 2]     = *reinterpret_cast<uint32_t*>(&h01);
            hh[s * 2 + 1] = *reinterpret_cast<uint32_t*>(&h23);
            // sum the fp16-ROUNDED values so numerator/denominator errors cancel
            float2 c01 = __half22float2(h01), c23 = __half22float2(h23);
            Spart += (c01.x + c01.y) + (c23.x + c23.y);
        }
        *reinterpret_cast<uint4*>(&WsB[r][jq * 32 + q * 4]) =
            make_uint4(hh[0], hh[1], hh[2], hh[3]);
    }
}

// ---------------------------------------------------------------------------
// Kernel 4: fused masked-softmax @ Wh.
// Adjacency streams through a 3-stage cp.async smem ring (issued 2 tiles
// ahead, ~48-64KB in flight per SM) -> bandwidth no longer register-window
// limited. Per phase: commit Bs(c+1), commit Adj(c+2), MMA(c), wait_group 1,
// gen(c+1).
// ---------------------------------------------------------------------------
__global__ __launch_bounds__(256, 1) void k_main(const int* __restrict__ adj,
                                                 float* __restrict__ out) {
    extern __shared__ __align__(16) char smem[];
    __half(*WsA[2])[WS_STRIDE];
    __half(*BsA[2])[BS_STRIDE];
    WsA[0] = reinterpret_cast<__half(*)[WS_STRIDE]>(smem);
    WsA[1] = reinterpret_cast<__half(*)[WS_STRIDE]>(smem + WS_BYTES);
    BsA[0] = reinterpret_cast<__half(*)[BS_STRIDE]>(smem + 2 * WS_BYTES);
    BsA[1] = reinterpret_cast<__half(*)[BS_STRIDE]>(smem + 2 * WS_BYTES + BS_BYTES);
    int* AsA[3];
    AsA[0] = reinterpret_cast<int*>(smem + 2 * WS_BYTES + 2 * BS_BYTES);
    AsA[1] = reinterpret_cast<int*>(smem + 2 * WS_BYTES + 2 * BS_BYTES + AS_BYTES);
    AsA[2] = reinterpret_cast<int*>(smem + 2 * WS_BYTES + 2 * BS_BYTES + 2 * AS_BYTES);

    const int tid  = threadIdx.x;
    const int lane = tid & 31, wid = tid >> 5;
    const int wm = wid & 3;
    const int wn = wid >> 2;
    const int i0 = blockIdx.x * MT;

    // gen mapping (transposed for bank-conflict-free smem)
    const int r  = tid & 63;
    const int jq = tid >> 6;
    // Bs cp.async mapping: 2 threads per j-row, 64 halves each
    const int jb   = tid >> 1;
    const int boff = (tid & 1) * 64;
    // Adj cp.async mapping: 4 threads per row, 128B each
    const int ar  = tid >> 2;
    const int seg = tid & 3;

    const float f1r = g_f1[i0 + r];
    const float Mr  = g_M[i0 + r];

    const uint32_t bdst[2] = {s2u(&BsA[0][jb][boff]), s2u(&BsA[1][jb][boff])};
    const __half* bsrc_base = g_Whh + (size_t)jb * OUT_DIM + boff;

    const uint32_t adst[3] = {s2u(AsA[0] + ar * AS_STRIDE + seg * 32),
                              s2u(AsA[1] + ar * AS_STRIDE + seg * 32),
                              s2u(AsA[2] + ar * AS_STRIDE + seg * 32)};
    const int* asrc_base = adj + (size_t)(i0 + ar) * N_NODES + seg * 32;

    float acc[8][4];
#pragma unroll
    for (int n = 0; n < 8; n++)
#pragma unroll
        for (int e = 0; e < 4; e++) acc[n][e] = 0.f;
    float Spart = 0.f;

    // ---- prologue: G1=adj0, G2=bs0, G3=adj1; wait_group 1 leaves adj1 flying
#pragma unroll
    for (int q = 0; q < 8; q++) cpasync16(adst[0] + q * 16, asrc_base + q * 4);
    CP_COMMIT();
#pragma unroll
    for (int q = 0; q < 8; q++) cpasync16(bdst[0] + q * 16, bsrc_base + q * 8);
    CP_COMMIT();
#pragma unroll
    for (int q = 0; q < 8; q++) cpasync16(adst[1] + q * 16, asrc_base + KT + q * 4);
    CP_COMMIT();
    CP_WAIT1();
    __syncthreads();
    gen_tile(AsA[0], 0, WsA[0], r, jq, f1r, Mr, Spart);
    __syncthreads();

#pragma unroll 1
    for (int cur = 0; cur < NTILES; cur++) {
        const int ph = cur & 1;

        // 1. commit Bs(cur+1)
        if (cur + 1 < NTILES) {
            const __half* bsrc = bsrc_base + (size_t)(cur + 1) * KT * OUT_DIM;
#pragma unroll
            for (int q = 0; q < 8; q++) cpasync16(bdst[ph ^ 1] + q * 16, bsrc + q * 8);
            CP_COMMIT();
        }
        // 2. commit Adj(cur+2) into ring stage (cur+2)%3
        if (cur + 2 < NTILES) {
            const int st = (cur + 2) % 3;
            const int* asrc = asrc_base + (cur + 2) * KT;
#pragma unroll
            for (int q = 0; q < 8; q++) cpasync16(adst[st] + q * 16, asrc + q * 4);
            CP_COMMIT();
        }

        // 3. MMA on current buffers
        __half(*WsC)[WS_STRIDE] = WsA[ph];
        __half(*BsC)[BS_STRIDE] = BsA[ph];
#pragma unroll
        for (int ks = 0; ks < KT / 16; ks++) {
            uint32_t a0, a1, a2, a3;
            uint32_t aaddr = s2u(&WsC[wm * 16 + (lane & 15)][ks * 16 + (lane >> 4) * 8]);
            asm volatile("ldmatrix.sync.aligned.m8n8.x4.shared.b16 {%0,%1,%2,%3}, [%4];"
                         : "=r"(a0), "=r"(a1), "=r"(a2), "=r"(a3)
                         : "r"(aaddr));
#pragma unroll
            for (int bn = 0; bn < 4; bn++) {
                uint32_t b0, b1, b2, b3;
                uint32_t baddr =
                    s2u(&BsC[ks * 16 + (lane & 15)][wn * 64 + bn * 16 + (lane >> 4) * 8]);
                asm volatile("ldmatrix.sync.aligned.m8n8.x4.trans.shared.b16 {%0,%1,%2,%3}, [%4];"
                             : "=r"(b0), "=r"(b1), "=r"(b2), "=r"(b3)
                             : "r"(baddr));
                mma16816(acc[2 * bn],     a0, a1, a2, a3, b0, b1);
                mma16816(acc[2 * bn + 1], a0, a1, a2, a3, b2, b3);
            }
        }

        // 4. retire {Adj(cur+1), Bs(cur+1)}; keep Adj(cur+2) in flight
        if (cur + 2 < NTILES) { CP_WAIT1(); } else { CP_WAIT0(); }
        __syncthreads();

        // 5. generate next W tile
        if (cur + 1 < NTILES)
            gen_tile(AsA[(cur + 1) % 3], (cur + 1) * KT, WsA[ph ^ 1], r, jq, f1r, Mr, Spart);
        __syncthreads();
    }

    // ---- epilogue: row sums, softmax scale, ELU ----
    float* Ssum = reinterpret_cast<float*>(smem);
    Ssum[r * 4 + jq] = Spart;
    __syncthreads();

    const int g    = lane >> 2;
    const int row0 = wm * 16 + g;
    const int row1 = row0 + 8;
    float S0 = Ssum[row0 * 4] + Ssum[row0 * 4 + 1] + Ssum[row0 * 4 + 2] + Ssum[row0 * 4 + 3];
    float S1 = Ssum[row1 * 4] + Ssum[row1 * 4 + 1] + Ssum[row1 * 4 + 2] + Ssum[row1 * 4 + 3];
    float inv0 = 1.f / S0, inv1 = 1.f / S1;

#pragma unroll
    for (int nt = 0; nt < 8; nt++) {
        int cn = wn * 64 + nt * 8 + 2 * (lane & 3);
        size_t o0 = (size_t)(i0 + row0) * OUT_DIM + cn;
        size_t o1 = (size_t)(i0 + row1) * OUT_DIM + cn;
        float v0 = acc[nt][0] * inv0, v1 = acc[nt][1] * inv0;
        float v2 = acc[nt][2] * inv1, v3 = acc[nt][3] * inv1;
        float2 r01 = make_float2(v0 > 0.f ? v0 : __expf(v0) - 1.f,
                                 v1 > 0.f ? v1 : __expf(v1) - 1.f);
        float2 r23 = make_float2(v2 > 0.f ? v2 : __expf(v2) - 1.f,
                                 v3 > 0.f ? v3 : __expf(v3) - 1.f);
        *reinterpret_cast<float2*>(out + o0) = r01;
        *reinterpret_cast<float2*>(out + o1) = r23;
    }
}

// ---------------------------------------------------------------------------
extern "C" void kernel_launch(void* const* d_in, const int* in_sizes, int n_in,
                              void* d_out, int out_size) {
    const int*   adj = (const int*)d_in[0];
    const float* X   = (const float*)d_in[1];
    const float* W   = (const float*)d_in[2];
    const float* a   = (const float*)d_in[3];
    float* out = (float*)d_out;

    cudaFuncSetAttribute(k_main, cudaFuncAttributeMaxDynamicSharedMemorySize, SMEM_BYTES);

    k_wh<<<N_NODES / 16, 256>>>(X, W, a);
    k_max<<<1, 256>>>();
    k_prep<<<N_NODES / 256, 256>>>();
    k_main<<<N_NODES / MT, 256, SMEM_BYTES>>>(adj, out);
}

// round 5
// speedup vs baseline: 1.2521x; 1.1759x over previous
#include <cuda_runtime.h>
#include <cuda_fp16.h>
#include <cstdint>
#include <cstddef>

#define N_NODES 8192
#define IN_DIM  256
#define OUT_DIM 128
#define ALPHA   0.2f
#define MT      32       // rows per CTA (grid 256 -> 2 CTAs/SM)
#define KT      128      // j per tile
#define NTILES  (N_NODES / KT)   // 64
#define WPR     (N_NODES / 32)   // 256 mask words per row

#define WS_STRIDE (KT + 8)       // 136 halves
#define BS_STRIDE (OUT_DIM + 8)  // 136 halves
#define WS_BYTES  (MT * WS_STRIDE * 2)    // 8704
#define BS_BYTES  (KT * BS_STRIDE * 2)    // 34816
#define SMEM_BYTES (2 * WS_BYTES + 2 * BS_BYTES)  // 87040 -> 2 CTAs/SM

#define WH_BLOCKS (N_NODES / 16)   // 512 GEMM blocks fused into k_pre

// Scratch (device globals: no allocation allowed)
__device__ __half   g_Whh [N_NODES * OUT_DIM];
__device__ uint32_t g_abits[N_NODES * WPR];     // 8 MB packed adjacency
__device__ float    g_f1 [N_NODES];
__device__ float    g_f2 [N_NODES];
__device__ float    g_M  [N_NODES];
__device__ float    g_c;

// ---------------------------------------------------------------------------
// Kernel 1 (fused): blocks [0,512): Wh = X@W + f1/f2;  blocks [512,...):
// pack adjacency to bits (1 row per block, 8 warps x 1024 ints, ballot).
// The FMA-heavy GEMM hides inside the BW-heavy pack stream.
// ---------------------------------------------------------------------------
__global__ __launch_bounds__(256) void k_pre(const float* __restrict__ X,
                                             const float* __restrict__ W,
                                             const float* __restrict__ a,
                                             const int* __restrict__ adj) {
    const int tid = threadIdx.x;

    if (blockIdx.x >= WH_BLOCKS) {
        // ---- pack part: one adjacency row per block ----
        const int row  = blockIdx.x - WH_BLOCKS;
        const int w    = tid >> 5;
        const int lane = tid & 31;
        const int* src = adj + (size_t)row * N_NODES + w * 1024;
        uint32_t myword = 0;
#pragma unroll
        for (int k = 0; k < 32; k++) {
            int v = src[k * 32 + lane];
            uint32_t b = __ballot_sync(0xffffffffu, v > 0);
            if (lane == k) myword = b;
        }
        g_abits[(size_t)row * WPR + w * 32 + lane] = myword;
        return;
    }

    // ---- GEMM part: 16 rows of Wh per block ----
    __shared__ float xs[16][IN_DIM];
    const int i0 = blockIdx.x * 16;

    const float4* Xv  = reinterpret_cast<const float4*>(X + (size_t)i0 * IN_DIM);
    float4*       xsv = reinterpret_cast<float4*>(&xs[0][0]);
#pragma unroll
    for (int q = 0; q < 4; q++) xsv[tid + q * 256] = Xv[tid + q * 256];
    __syncthreads();

    const int cg = tid & 31;
    const int rp = tid >> 5;
    const int r0 = rp * 2, r1 = r0 + 1;
    const int c4 = cg * 4;

    const float4* Wv = reinterpret_cast<const float4*>(W);
    float4 acc0 = {0.f, 0.f, 0.f, 0.f};
    float4 acc1 = {0.f, 0.f, 0.f, 0.f};
#pragma unroll 8
    for (int k = 0; k < IN_DIM; k++) {
        float4 w  = Wv[k * 32 + cg];
        float  x0 = xs[r0][k];
        float  x1 = xs[r1][k];
        acc0.x = fmaf(x0, w.x, acc0.x); acc0.y = fmaf(x0, w.y, acc0.y);
        acc0.z = fmaf(x0, w.z, acc0.z); acc0.w = fmaf(x0, w.w, acc0.w);
        acc1.x = fmaf(x1, w.x, acc1.x); acc1.y = fmaf(x1, w.y, acc1.y);
        acc1.z = fmaf(x1, w.z, acc1.z); acc1.w = fmaf(x1, w.w, acc1.w);
    }
    {
        __half2 h00 = __floats2half2_rn(acc0.x, acc0.y);
        __half2 h01 = __floats2half2_rn(acc0.z, acc0.w);
        __half2 h10 = __floats2half2_rn(acc1.x, acc1.y);
        __half2 h11 = __floats2half2_rn(acc1.z, acc1.w);
        __half2* p0 = reinterpret_cast<__half2*>(g_Whh + (size_t)(i0 + r0) * OUT_DIM + c4);
        __half2* p1 = reinterpret_cast<__half2*>(g_Whh + (size_t)(i0 + r1) * OUT_DIM + c4);
        p0[0] = h00; p0[1] = h01;
        p1[0] = h10; p1[1] = h11;
    }
    float p1 = acc0.x * a[c4] + acc0.y * a[c4 + 1] + acc0.z * a[c4 + 2] + acc0.w * a[c4 + 3];
    float q1 = acc0.x * a[128 + c4] + acc0.y * a[128 + c4 + 1] +
               acc0.z * a[128 + c4 + 2] + acc0.w * a[128 + c4 + 3];
    float p2 = acc1.x * a[c4] + acc1.y * a[c4 + 1] + acc1.z * a[c4 + 2] + acc1.w * a[c4 + 3];
    float q2 = acc1.x * a[128 + c4] + acc1.y * a[128 + c4 + 1] +
               acc1.z * a[128 + c4 + 2] + acc1.w * a[128 + c4 + 3];
#pragma unroll
    for (int off = 16; off; off >>= 1) {
        p1 += __shfl_xor_sync(0xffffffffu, p1, off);
        q1 += __shfl_xor_sync(0xffffffffu, q1, off);
        p2 += __shfl_xor_sync(0xffffffffu, p2, off);
        q2 += __shfl_xor_sync(0xffffffffu, q2, off);
    }
    if (cg == 0) {
        g_f1[i0 + r0] = p1; g_f2[i0 + r0] = q1;
        g_f1[i0 + r1] = p2; g_f2[i0 + r1] = q2;
    }
}

__global__ __launch_bounds__(256) void k_max() {
    __shared__ float red[8];
    int t = threadIdx.x;
    float m = -1e30f;
    for (int i = t; i < N_NODES; i += 256) m = fmaxf(m, g_f2[i]);
#pragma unroll
    for (int off = 16; off; off >>= 1) m = fmaxf(m, __shfl_xor_sync(0xffffffffu, m, off));
    if ((t & 31) == 0) red[t >> 5] = m;
    __syncthreads();
    if (t == 0) {
        float mm = red[0];
#pragma unroll
        for (int i = 1; i < 8; i++) mm = fmaxf(mm, red[i]);
        g_c = mm;
    }
}

__global__ __launch_bounds__(256) void k_prep() {
    int i = blockIdx.x * 256 + threadIdx.x;
    float s = g_f1[i] + g_c;
    g_M[i] = fmaxf(s, ALPHA * s);
}

__device__ __forceinline__ uint32_t s2u(const void* p) {
    return (uint32_t)__cvta_generic_to_shared(p);
}
__device__ __forceinline__ void cpasync16(uint32_t dst, const void* src) {
    asm volatile("cp.async.cg.shared.global [%0], [%1], 16;\n" :: "r"(dst), "l"(src));
}
#define CP_COMMIT() asm volatile("cp.async.commit_group;\n" ::: "memory")
#define CP_WAIT0()  asm volatile("cp.async.wait_group 0;\n" ::: "memory")

__device__ __forceinline__ void mma16816(float* d, uint32_t a0, uint32_t a1, uint32_t a2,
                                         uint32_t a3, uint32_t b0, uint32_t b1) {
    asm volatile(
        "mma.sync.aligned.m16n8k16.row.col.f32.f16.f16.f32 "
        "{%0,%1,%2,%3},{%4,%5,%6,%7},{%8,%9},{%0,%1,%2,%3};\n"
        : "+f"(d[0]), "+f"(d[1]), "+f"(d[2]), "+f"(d[3])
        : "r"(a0), "r"(a1), "r"(a2), "r"(a3), "r"(b0), "r"(b1));
}

// generate one 32x128 fp16 weight tile; mask = this thread's 16-j bit window
// thread map: r = tid&31 (row, == lane), jqh = tid>>5 (16-j chunk, == warp id)
__device__ __forceinline__ void gen_tile(uint32_t mask, int jt,
                                         __half (*WsB)[WS_STRIDE],
                                         int r, int jqh, float f1r, float Mr,
                                         float& Spart) {
    const uint32_t mk = mask >> ((jqh & 1) * 16);
#pragma unroll
    for (int q = 0; q < 4; q += 2) {
        uint32_t hh[4];
#pragma unroll
        for (int s = 0; s < 2; s++) {
            float4 f2v = *reinterpret_cast<const float4*>(g_f2 + jt + jqh * 16 + (q + s) * 4);
            uint32_t bits = mk >> ((q + s) * 4);
            float s0 = f1r + f2v.x, s1 = f1r + f2v.y;
            float s2 = f1r + f2v.z, s3 = f1r + f2v.w;
            float w0 = (bits & 1u) ? __expf(fmaxf(s0, ALPHA * s0) - Mr) : 0.f;
            float w1 = (bits & 2u) ? __expf(fmaxf(s1, ALPHA * s1) - Mr) : 0.f;
            float w2 = (bits & 4u) ? __expf(fmaxf(s2, ALPHA * s2) - Mr) : 0.f;
            float w3 = (bits & 8u) ? __expf(fmaxf(s3, ALPHA * s3) - Mr) : 0.f;
            __half2 h01 = __floats2half2_rn(w0, w1);
            __half2 h23 = __floats2half2_rn(w2, w3);
            hh[s * 2]     = *reinterpret_cast<uint32_t*>(&h01);
            hh[s * 2 + 1] = *reinterpret_cast<uint32_t*>(&h23);
            // sum the fp16-ROUNDED values so numerator/denominator errors cancel
            float2 c01 = __half22float2(h01), c23 = __half22float2(h23);
            Spart += (c01.x + c01.y) + (c23.x + c23.y);
        }
        *reinterpret_cast<uint4*>(&WsB[r][jqh * 16 + q * 4]) =
            make_uint4(hh[0], hh[1], hh[2], hh[3]);
    }
}

// ---------------------------------------------------------------------------
// Kernel 4: fused masked-softmax @ Wh with bitmask adjacency.
// CTA = 32 rows; grid 256 -> 2 CTAs/SM. Per phase: commit Bs(c+1),
// ldg mask(c+2), MMA(c), gen(c+1), wait+single barrier.
// ---------------------------------------------------------------------------
__global__ __launch_bounds__(256, 2) void k_main(float* __restrict__ out) {
    extern __shared__ __align__(16) char smem[];
    __half(*WsA[2])[WS_STRIDE];
    __half(*BsA[2])[BS_STRIDE];
    WsA[0] = reinterpret_cast<__half(*)[WS_STRIDE]>(smem);
    WsA[1] = reinterpret_cast<__half(*)[WS_STRIDE]>(smem + WS_BYTES);
    BsA[0] = reinterpret_cast<__half(*)[BS_STRIDE]>(smem + 2 * WS_BYTES);
    BsA[1] = reinterpret_cast<__half(*)[BS_STRIDE]>(smem + 2 * WS_BYTES + BS_BYTES);

    const int tid  = threadIdx.x;
    const int lane = tid & 31, wid = tid >> 5;
    const int wm = wid & 1;        // 2 row-slices of 16
    const int wn = wid >> 1;       // 4 col-slices of 32
    const int i0 = blockIdx.x * MT;

    // gen mapping
    const int r   = tid & 31;
    const int jqh = tid >> 5;
    // Bs cp.async mapping: 2 threads per j-row, 64 halves each
    const int jb   = tid >> 1;
    const int boff = (tid & 1) * 64;

    const float f1r = g_f1[i0 + r];
    const float Mr  = g_M[i0 + r];

    const uint32_t bdst[2] = {s2u(&BsA[0][jb][boff]), s2u(&BsA[1][jb][boff])};
    const __half* bsrc_base = g_Whh + (size_t)jb * OUT_DIM + boff;

    // mask word for tile t: g_abits[(i0+r)*WPR + t*4 + (jqh>>1)]
    const uint32_t* mrow = g_abits + (size_t)(i0 + r) * WPR + (jqh >> 1);

    float acc[4][4];
#pragma unroll
    for (int n = 0; n < 4; n++)
#pragma unroll
        for (int e = 0; e < 4; e++) acc[n][e] = 0.f;
    float Spart = 0.f;

    // ---- prologue ----
    uint32_t mA = __ldg(mrow);        // tile 0
    uint32_t mB = __ldg(mrow + 4);    // tile 1
#pragma unroll
    for (int q = 0; q < 8; q++) cpasync16(bdst[0] + q * 16, bsrc_base + q * 8);
    CP_COMMIT();
    gen_tile(mA, 0, WsA[0], r, jqh, f1r, Mr, Spart);
    CP_WAIT0();
    __syncthreads();

#pragma unroll 1
    for (int cur = 0; cur < NTILES; cur++) {
        const int ph = cur & 1;

        // 1. commit Bs(cur+1)
        if (cur + 1 < NTILES) {
            const __half* bsrc = bsrc_base + (size_t)(cur + 1) * KT * OUT_DIM;
#pragma unroll
            for (int q = 0; q < 8; q++) cpasync16(bdst[ph ^ 1] + q * 16, bsrc + q * 8);
            CP_COMMIT();
        }
        // 2. prefetch mask(cur+2)
        uint32_t mC = (cur + 2 < NTILES) ? __ldg(mrow + (size_t)(cur + 2) * 4) : 0u;

        // 3. MMA on current buffers
        __half(*WsC)[WS_STRIDE] = WsA[ph];
        __half(*BsC)[BS_STRIDE] = BsA[ph];
#pragma unroll
        for (int ks = 0; ks < KT / 16; ks++) {
            uint32_t a0, a1, a2, a3;
            uint32_t aaddr = s2u(&WsC[wm * 16 + (lane & 15)][ks * 16 + (lane >> 4) * 8]);
            asm volatile("ldmatrix.sync.aligned.m8n8.x4.shared.b16 {%0,%1,%2,%3}, [%4];"
                         : "=r"(a0), "=r"(a1), "=r"(a2), "=r"(a3)
                         : "r"(aaddr));
#pragma unroll
            for (int bn = 0; bn < 2; bn++) {
                uint32_t b0, b1, b2, b3;
                uint32_t baddr =
                    s2u(&BsC[ks * 16 + (lane & 15)][wn * 32 + bn * 16 + (lane >> 4) * 8]);
                asm volatile("ldmatrix.sync.aligned.m8n8.x4.trans.shared.b16 {%0,%1,%2,%3}, [%4];"
                             : "=r"(b0), "=r"(b1), "=r"(b2), "=r"(b3)
                             : "r"(baddr));
                mma16816(acc[2 * bn],     a0, a1, a2, a3, b0, b1);
                mma16816(acc[2 * bn + 1], a0, a1, a2, a3, b2, b3);
            }
        }

        // 4. generate next W tile into the other Ws buffer
        if (cur + 1 < NTILES)
            gen_tile(mB, (cur + 1) * KT, WsA[ph ^ 1], r, jqh, f1r, Mr, Spart);
        mB = mC;

        // 5. single barrier: Bs arrived + gen visible
        CP_WAIT0();
        __syncthreads();
    }

    // ---- epilogue: row sums (8 partials/row), softmax scale, ELU ----
    float* Ssum = reinterpret_cast<float*>(smem);
    Ssum[r * 8 + jqh] = Spart;
    __syncthreads();

    const int g    = lane >> 2;
    const int row0 = wm * 16 + g;
    const int row1 = row0 + 8;
    float4 sa = *reinterpret_cast<const float4*>(Ssum + row0 * 8);
    float4 sb = *reinterpret_cast<const float4*>(Ssum + row0 * 8 + 4);
    float4 sc = *reinterpret_cast<const float4*>(Ssum + row1 * 8);
    float4 sd = *reinterpret_cast<const float4*>(Ssum + row1 * 8 + 4);
    float S0 = (sa.x + sa.y + sa.z + sa.w) + (sb.x + sb.y + sb.z + sb.w);
    float S1 = (sc.x + sc.y + sc.z + sc.w) + (sd.x + sd.y + sd.z + sd.w);
    float inv0 = 1.f / S0, inv1 = 1.f / S1;

#pragma unroll
    for (int nt = 0; nt < 4; nt++) {
        int cn = wn * 32 + nt * 8 + 2 * (lane & 3);
        size_t o0 = (size_t)(i0 + row0) * OUT_DIM + cn;
        size_t o1 = (size_t)(i0 + row1) * OUT_DIM + cn;
        float v0 = acc[nt][0] * inv0, v1 = acc[nt][1] * inv0;
        float v2 = acc[nt][2] * inv1, v3 = acc[nt][3] * inv1;
        float2 r01 = make_float2(v0 > 0.f ? v0 : __expf(v0) - 1.f,
                                 v1 > 0.f ? v1 : __expf(v1) - 1.f);
        float2 r23 = make_float2(v2 > 0.f ? v2 : __expf(v2) - 1.f,
                                 v3 > 0.f ? v3 : __expf(v3) - 1.f);
        *reinterpret_cast<float2*>(out + o0) = r01;
        *reinterpret_cast<float2*>(out + o1) = r23;
    }
}

// ---------------------------------------------------------------------------
extern "C" void kernel_launch(void* const* d_in, const int* in_sizes, int n_in,
                              void* d_out, int out_size) {
    const int*   adj = (const int*)d_in[0];
    const float* X   = (const float*)d_in[1];
    const float* W   = (const float*)d_in[2];
    const float* a   = (const float*)d_in[3];
    float* out = (float*)d_out;

    cudaFuncSetAttribute(k_main, cudaFuncAttributeMaxDynamicSharedMemorySize, SMEM_BYTES);

    k_pre<<<WH_BLOCKS + N_NODES, 256>>>(X, W, a, adj);
    k_max<<<1, 256>>>();
    k_prep<<<N_NODES / 256, 256>>>();
    k_main<<<N_NODES / MT, 256, SMEM_BYTES>>>(out);
}

// round 7
// speedup vs baseline: 1.4217x; 1.1354x over previous
#include <cuda_runtime.h>
#include <cuda_fp16.h>
#include <cstdint>
#include <cstddef>

#define N_NODES 8192
#define IN_DIM  256
#define OUT_DIM 128
#define ALPHA   0.2f
#define MT      32       // rows per CTA
#define KT      128      // j per tile
#define NTILES  (N_NODES / KT)   // 64
#define WPR     (N_NODES / 32)   // 256 mask words per row
#define NTHREADS 512

#define WS_STRIDE (KT + 8)       // 136 halves
#define BS_STRIDE (OUT_DIM + 8)  // 136 halves
#define WS_BYTES  (MT * WS_STRIDE * 2)    // 8704
#define BS_BYTES  (KT * BS_STRIDE * 2)    // 34816
#define SMEM_BYTES (2 * WS_BYTES + 2 * BS_BYTES)  // 87040 -> 2 CTAs/SM

#define WH_BLOCKS (N_NODES / 16)   // 512 GEMM blocks fused into k_pre

// Scratch (device globals: no allocation allowed)
__device__ __half   g_Whh [N_NODES * OUT_DIM];
__device__ uint32_t g_abits[N_NODES * WPR];     // 8 MB packed adjacency
__device__ float    g_f1 [N_NODES];
__device__ float    g_f2 [N_NODES];
__device__ float    g_M  [N_NODES];
__device__ float    g_c;

// ---------------------------------------------------------------------------
// Kernel 1 (fused): blocks [0,512): Wh = X@W + f1/f2;  blocks [512,...):
// pack one adjacency row to bits (int4 loads + nibble shfl-reduce).
// ---------------------------------------------------------------------------
__global__ __launch_bounds__(256) void k_pre(const float* __restrict__ X,
                                             const float* __restrict__ W,
                                             const float* __restrict__ a,
                                             const int* __restrict__ adj) {
    const int tid = threadIdx.x;

    if (blockIdx.x >= WH_BLOCKS) {
        // ---- pack: one row per block, 8 warps x 1024 ints via int4 ----
        const int row  = blockIdx.x - WH_BLOCKS;
        const int w    = tid >> 5;
        const int lane = tid & 31;
        const int4* src4 =
            reinterpret_cast<const int4*>(adj + (size_t)row * N_NODES + w * 1024);
        uint32_t myword = 0;
#pragma unroll
        for (int k = 0; k < 8; k++) {
            int4 v = src4[k * 32 + lane];
            uint32_t nib = (uint32_t)(v.x > 0) | ((uint32_t)(v.y > 0) << 1) |
                           ((uint32_t)(v.z > 0) << 2) | ((uint32_t)(v.w > 0) << 3);
            uint32_t key = nib << ((lane & 7) * 4);
            key |= __shfl_xor_sync(0xffffffffu, key, 1);
            key |= __shfl_xor_sync(0xffffffffu, key, 2);
            key |= __shfl_xor_sync(0xffffffffu, key, 4);
            if ((lane & 7) == k) myword = key;  // lane L: word for k=L&7, group g=L>>3
        }
        g_abits[(size_t)row * WPR + w * 32 + (lane & 7) * 4 + (lane >> 3)] = myword;
        return;
    }

    // ---- GEMM part: 16 rows of Wh per block ----
    __shared__ float xs[16][IN_DIM];
    const int i0 = blockIdx.x * 16;

    const float4* Xv  = reinterpret_cast<const float4*>(X + (size_t)i0 * IN_DIM);
    float4*       xsv = reinterpret_cast<float4*>(&xs[0][0]);
#pragma unroll
    for (int q = 0; q < 4; q++) xsv[tid + q * 256] = Xv[tid + q * 256];
    __syncthreads();

    const int cg = tid & 31;
    const int rp = tid >> 5;
    const int r0 = rp * 2, r1 = r0 + 1;
    const int c4 = cg * 4;

    const float4* Wv = reinterpret_cast<const float4*>(W);
    float4 acc0 = {0.f, 0.f, 0.f, 0.f};
    float4 acc1 = {0.f, 0.f, 0.f, 0.f};
#pragma unroll 8
    for (int k = 0; k < IN_DIM; k++) {
        float4 w  = Wv[k * 32 + cg];
        float  x0 = xs[r0][k];
        float  x1 = xs[r1][k];
        acc0.x = fmaf(x0, w.x, acc0.x); acc0.y = fmaf(x0, w.y, acc0.y);
        acc0.z = fmaf(x0, w.z, acc0.z); acc0.w = fmaf(x0, w.w, acc0.w);
        acc1.x = fmaf(x1, w.x, acc1.x); acc1.y = fmaf(x1, w.y, acc1.y);
        acc1.z = fmaf(x1, w.z, acc1.z); acc1.w = fmaf(x1, w.w, acc1.w);
    }
    {
        __half2 h00 = __floats2half2_rn(acc0.x, acc0.y);
        __half2 h01 = __floats2half2_rn(acc0.z, acc0.w);
        __half2 h10 = __floats2half2_rn(acc1.x, acc1.y);
        __half2 h11 = __floats2half2_rn(acc1.z, acc1.w);
        __half2* p0 = reinterpret_cast<__half2*>(g_Whh + (size_t)(i0 + r0) * OUT_DIM + c4);
        __half2* p1 = reinterpret_cast<__half2*>(g_Whh + (size_t)(i0 + r1) * OUT_DIM + c4);
        p0[0] = h00; p0[1] = h01;
        p1[0] = h10; p1[1] = h11;
    }
    float p1 = acc0.x * a[c4] + acc0.y * a[c4 + 1] + acc0.z * a[c4 + 2] + acc0.w * a[c4 + 3];
    float q1 = acc0.x * a[128 + c4] + acc0.y * a[128 + c4 + 1] +
               acc0.z * a[128 + c4 + 2] + acc0.w * a[128 + c4 + 3];
    float p2 = acc1.x * a[c4] + acc1.y * a[c4 + 1] + acc1.z * a[c4 + 2] + acc1.w * a[c4 + 3];
    float q2 = acc1.x * a[128 + c4] + acc1.y * a[128 + c4 + 1] +
               acc1.z * a[128 + c4 + 2] + acc1.w * a[128 + c4 + 3];
#pragma unroll
    for (int off = 16; off; off >>= 1) {
        p1 += __shfl_xor_sync(0xffffffffu, p1, off);
        q1 += __shfl_xor_sync(0xffffffffu, q1, off);
        p2 += __shfl_xor_sync(0xffffffffu, p2, off);
        q2 += __shfl_xor_sync(0xffffffffu, q2, off);
    }
    if (cg == 0) {
        g_f1[i0 + r0] = p1; g_f2[i0 + r0] = q1;
        g_f1[i0 + r1] = p2; g_f2[i0 + r1] = q2;
    }
}

__global__ __launch_bounds__(256) void k_max() {
    __shared__ float red[8];
    int t = threadIdx.x;
    float m = -1e30f;
    for (int i = t; i < N_NODES; i += 256) m = fmaxf(m, g_f2[i]);
#pragma unroll
    for (int off = 16; off; off >>= 1) m = fmaxf(m, __shfl_xor_sync(0xffffffffu, m, off));
    if ((t & 31) == 0) red[t >> 5] = m;
    __syncthreads();
    if (t == 0) {
        float mm = red[0];
#pragma unroll
        for (int i = 1; i < 8; i++) mm = fmaxf(mm, red[i]);
        g_c = mm;
    }
}

__global__ __launch_bounds__(256) void k_prep() {
    int i = blockIdx.x * 256 + threadIdx.x;
    float s = g_f1[i] + g_c;
    g_M[i] = fmaxf(s, ALPHA * s);
}

__device__ __forceinline__ uint32_t s2u(const void* p) {
    return (uint32_t)__cvta_generic_to_shared(p);
}
__device__ __forceinline__ void cpasync16(uint32_t dst, const void* src) {
    asm volatile("cp.async.cg.shared.global [%0], [%1], 16;\n" :: "r"(dst), "l"(src));
}
#define CP_COMMIT() asm volatile("cp.async.commit_group;\n" ::: "memory")
#define CP_WAIT0()  asm volatile("cp.async.wait_group 0;\n" ::: "memory")

__device__ __forceinline__ void mma16816(float* d, uint32_t a0, uint32_t a1, uint32_t a2,
                                         uint32_t a3, uint32_t b0, uint32_t b1) {
    asm volatile(
        "mma.sync.aligned.m16n8k16.row.col.f32.f16.f16.f32 "
        "{%0,%1,%2,%3},{%4,%5,%6,%7},{%8,%9},{%0,%1,%2,%3};\n"
        : "+f"(d[0]), "+f"(d[1]), "+f"(d[2]), "+f"(d[3])
        : "r"(a0), "r"(a1), "r"(a2), "r"(a3), "r"(b0), "r"(b1));
}

// generate 8 j-values of one W row from an 8-bit mask window
// thread map (512 thr): r = tid&31 (row), jo = tid>>5 (0..15, 8 j each)
__device__ __forceinline__ void gen8(uint32_t byte_bits, int jt,
                                     __half (*WsB)[WS_STRIDE],
                                     int r, int jo, float f1r, float Mr,
                                     float& Spart) {
    const float* f2p = g_f2 + jt + jo * 8;
    float4 fa = *reinterpret_cast<const float4*>(f2p);       // broadcast in warp
    float4 fb = *reinterpret_cast<const float4*>(f2p + 4);
    float s0 = f1r + fa.x, s1 = f1r + fa.y, s2 = f1r + fa.z, s3 = f1r + fa.w;
    float s4 = f1r + fb.x, s5 = f1r + fb.y, s6 = f1r + fb.z, s7 = f1r + fb.w;
    float w0 = (byte_bits & 1u)   ? __expf(fmaxf(s0, ALPHA * s0) - Mr) : 0.f;
    float w1 = (byte_bits & 2u)   ? __expf(fmaxf(s1, ALPHA * s1) - Mr) : 0.f;
    float w2 = (byte_bits & 4u)   ? __expf(fmaxf(s2, ALPHA * s2) - Mr) : 0.f;
    float w3 = (byte_bits & 8u)   ? __expf(fmaxf(s3, ALPHA * s3) - Mr) : 0.f;
    float w4 = (byte_bits & 16u)  ? __expf(fmaxf(s4, ALPHA * s4) - Mr) : 0.f;
    float w5 = (byte_bits & 32u)  ? __expf(fmaxf(s5, ALPHA * s5) - Mr) : 0.f;
    float w6 = (byte_bits & 64u)  ? __expf(fmaxf(s6, ALPHA * s6) - Mr) : 0.f;
    float w7 = (byte_bits & 128u) ? __expf(fmaxf(s7, ALPHA * s7) - Mr) : 0.f;
    __half2 h0 = __floats2half2_rn(w0, w1);
    __half2 h1 = __floats2half2_rn(w2, w3);
    __half2 h2 = __floats2half2_rn(w4, w5);
    __half2 h3 = __floats2half2_rn(w6, w7);
    *reinterpret_cast<uint4*>(&WsB[r][jo * 8]) =
        make_uint4(*reinterpret_cast<uint32_t*>(&h0), *reinterpret_cast<uint32_t*>(&h1),
                   *reinterpret_cast<uint32_t*>(&h2), *reinterpret_cast<uint32_t*>(&h3));
    // sum the fp16-ROUNDED values so numerator/denominator errors cancel
    float2 c0 = __half22float2(h0), c1 = __half22float2(h1);
    float2 c2 = __half22float2(h2), c3 = __half22float2(h3);
    Spart += ((c0.x + c0.y) + (c1.x + c1.y)) + ((c2.x + c2.y) + (c3.x + c3.y));
}

// ---------------------------------------------------------------------------
// Kernel 4: fused masked-softmax @ Wh, 512 threads (16 warps), 2 CTAs/SM.
// ---------------------------------------------------------------------------
__global__ __launch_bounds__(NTHREADS, 2) void k_main(float* __restrict__ out) {
    extern __shared__ __align__(16) char smem[];
    __half(*WsA[2])[WS_STRIDE];
    __half(*BsA[2])[BS_STRIDE];
    WsA[0] = reinterpret_cast<__half(*)[WS_STRIDE]>(smem);
    WsA[1] = reinterpret_cast<__half(*)[WS_STRIDE]>(smem + WS_BYTES);
    BsA[0] = reinterpret_cast<__half(*)[BS_STRIDE]>(smem + 2 * WS_BYTES);
    BsA[1] = reinterpret_cast<__half(*)[BS_STRIDE]>(smem + 2 * WS_BYTES + BS_BYTES);

    const int tid  = threadIdx.x;
    const int lane = tid & 31, wid = tid >> 5;
    const int wm = wid & 1;        // 2 row-slices of 16
    const int wn = wid >> 1;       // 8 col-slices of 16
    const int i0 = blockIdx.x * MT;

    // gen mapping
    const int r  = tid & 31;
    const int jo = tid >> 5;       // 16 chunks of 8 j
    // Bs cp.async mapping: 4 threads per j-row, 32 halves (4x16B) each
    const int jb = tid >> 2;
    const int bo = (tid & 3) * 32;

    const float f1r = g_f1[i0 + r];
    const float Mr  = g_M[i0 + r];

    const uint32_t bdst[2] = {s2u(&BsA[0][jb][bo]), s2u(&BsA[1][jb][bo])};
    const __half* bsrc_base = g_Whh + (size_t)jb * OUT_DIM + bo;

    // mask: word for tile t at mrow[t*4]; byte window = (jo&3)*8
    const uint32_t* mrow = g_abits + (size_t)(i0 + r) * WPR + (jo >> 2);
    const int msh = (jo & 3) * 8;

    float acc[2][4];
#pragma unroll
    for (int n = 0; n < 2; n++)
#pragma unroll
        for (int e = 0; e < 4; e++) acc[n][e] = 0.f;
    float Spart = 0.f;

    // ---- prologue ----
    uint32_t mwA = __ldg(mrow);       // word containing tile 0 byte
    uint32_t mwB = __ldg(mrow + 4);   // tile 1
#pragma unroll
    for (int q = 0; q < 4; q++) cpasync16(bdst[0] + q * 16, bsrc_base + q * 8);
    CP_COMMIT();
    gen8((mwA >> msh) & 0xffu, 0, WsA[0], r, jo, f1r, Mr, Spart);
    CP_WAIT0();
    __syncthreads();

#pragma unroll 1
    for (int cur = 0; cur < NTILES; cur++) {
        const int ph = cur & 1;

        // 1. commit Bs(cur+1)
        if (cur + 1 < NTILES) {
            const __half* bsrc = bsrc_base + (size_t)(cur + 1) * KT * OUT_DIM;
#pragma unroll
            for (int q = 0; q < 4; q++) cpasync16(bdst[ph ^ 1] + q * 16, bsrc + q * 8);
            CP_COMMIT();
        }
        // 2. prefetch mask word for tile cur+2
        uint32_t mwC = (cur + 2 < NTILES) ? __ldg(mrow + (size_t)(cur + 2) * 4) : 0u;

        // 3. MMA on current buffers (per warp: 16x16 out, 8 ks)
        __half(*WsC)[WS_STRIDE] = WsA[ph];
        __half(*BsC)[BS_STRIDE] = BsA[ph];
#pragma unroll
        for (int ks = 0; ks < KT / 16; ks++) {
            uint32_t a0, a1, a2, a3;
            uint32_t aaddr = s2u(&WsC[wm * 16 + (lane & 15)][ks * 16 + (lane >> 4) * 8]);
            asm volatile("ldmatrix.sync.aligned.m8n8.x4.shared.b16 {%0,%1,%2,%3}, [%4];"
                         : "=r"(a0), "=r"(a1), "=r"(a2), "=r"(a3)
                         : "r"(aaddr));
            uint32_t b0, b1, b2, b3;
            uint32_t baddr = s2u(&BsC[ks * 16 + (lane & 15)][wn * 16 + (lane >> 4) * 8]);
            asm volatile("ldmatrix.sync.aligned.m8n8.x4.trans.shared.b16 {%0,%1,%2,%3}, [%4];"
                         : "=r"(b0), "=r"(b1), "=r"(b2), "=r"(b3)
                         : "r"(baddr));
            mma16816(acc[0], a0, a1, a2, a3, b0, b1);
            mma16816(acc[1], a0, a1, a2, a3, b2, b3);
        }

        // 4. generate next W tile
        if (cur + 1 < NTILES)
            gen8((mwB >> msh) & 0xffu, (cur + 1) * KT, WsA[ph ^ 1], r, jo, f1r, Mr, Spart);
        mwB = mwC;

        // 5. single barrier: Bs arrived + gen visible
        CP_WAIT0();
        __syncthreads();
    }

    // ---- epilogue: row sums (16 partials/row), softmax scale, ELU ----
    float* Ssum = reinterpret_cast<float*>(smem);
    Ssum[r * 16 + jo] = Spart;
    __syncthreads();

    const int g    = lane >> 2;
    const int row0 = wm * 16 + g;
    const int row1 = row0 + 8;
    float S0, S1;
    {
        const float4* p = reinterpret_cast<const float4*>(Ssum + row0 * 16);
        float4 sa = p[0], sb = p[1], sc = p[2], sd = p[3];
        S0 = ((sa.x + sa.y + sa.z + sa.w) + (sb.x + sb.y + sb.z + sb.w)) +
             ((sc.x + sc.y + sc.z + sc.w) + (sd.x + sd.y + sd.z + sd.w));
        const float4* q = reinterpret_cast<const float4*>(Ssum + row1 * 16);
        float4 se = q[0], sf = q[1], sg = q[2], sh = q[3];
        S1 = ((se.x + se.y + se.z + se.w) + (sf.x + sf.y + sf.z + sf.w)) +
             ((sg.x + sg.y + sg.z + sg.w) + (sh.x + sh.y + sh.z + sh.w));
    }
    float inv0 = 1.f / S0, inv1 = 1.f / S1;

#pragma unroll
    for (int bn = 0; bn < 2; bn++) {
        int cn = wn * 16 + bn * 8 + 2 * (lane & 3);
        size_t o0 = (size_t)(i0 + row0) * OUT_DIM + cn;
        size_t o1 = (size_t)(i0 + row1) * OUT_DIM + cn;
        float v0 = acc[bn][0] * inv0, v1 = acc[bn][1] * inv0;
        float v2 = acc[bn][2] * inv1, v3 = acc[bn][3] * inv1;
        float2 r01 = make_float2(v0 > 0.f ? v0 : __expf(v0) - 1.f,
                                 v1 > 0.f ? v1 : __expf(v1) - 1.f);
        float2 r23 = make_float2(v2 > 0.f ? v2 : __expf(v2) - 1.f,
                                 v3 > 0.f ? v3 : __expf(v3) - 1.f);
        *reinterpret_cast<float2*>(out + o0) = r01;
        *reinterpret_cast<float2*>(out + o1) = r23;
    }
}

// ---------------------------------------------------------------------------
extern "C" void kernel_launch(void* const* d_in, const int* in_sizes, int n_in,
                              void* d_out, int out_size) {
    const int*   adj = (const int*)d_in[0];
    const float* X   = (const float*)d_in[1];
    const float* W   = (const float*)d_in[2];
    const float* a   = (const float*)d_in[3];
    float* out = (float*)d_out;

    cudaFuncSetAttribute(k_main, cudaFuncAttributeMaxDynamicSharedMemorySize, SMEM_BYTES);

    k_pre<<<WH_BLOCKS + N_NODES, 256>>>(X, W, a, adj);
    k_max<<<1, 256>>>();
    k_prep<<<N_NODES / 256, 256>>>();
    k_main<<<N_NODES / MT, NTHREADS, SMEM_BYTES>>>(out);
}